// round 14
// baseline (speedup 1.0000x reference)
#include <cuda_runtime.h>
#include <math.h>

#define N_NODES 20000
#define N_EDGES 320000
#define D 128
#define ETOT (N_EDGES + N_NODES)   // edges + self-loops = 340000
#define NG 64

// ---------------- scratch (device globals; no allocation allowed) ----------------
__device__ float g_bufA[N_NODES * D];
__device__ float g_bufB[N_NODES * D];
__device__ float g_hg[N_NODES * D];     // h @ gat_W
__device__ float g_hc[N_NODES * D];     // dinv[s] * (h @ gcn_W)   (dinv folded in)
__device__ float g_esp[2 * N_NODES];    // partial hg.a_src per column-half (plain stores)
__device__ float g_edp[2 * N_NODES];    // partial hg.a_dst per column-half
__device__ float g_dinv[N_NODES];       // deg^-1/2
__device__ float g_pooled[NG * D];
__device__ float g_cnt[NG];
// CSR (built once; degrees are layer-invariant)
__device__ int g_degi[N_NODES];
__device__ int g_rowptr[N_NODES + 1];
__device__ int g_cursor[N_NODES];
__device__ int g_esrc[ETOT];            // src node per CSR slot (grouped by dst)

// ---------------- helpers ----------------
__device__ __forceinline__ unsigned f2tf32(float a) {
    unsigned r;
    asm("cvt.rna.tf32.f32 %0, %1;" : "=r"(r) : "f"(a));
    return r;
}

__device__ __forceinline__ void mma_tf32(float* c, unsigned a0, unsigned a1, unsigned a2,
                                         unsigned a3, unsigned b0, unsigned b1) {
    asm volatile(
        "mma.sync.aligned.m16n8k8.row.col.f32.tf32.tf32.f32 "
        "{%0,%1,%2,%3}, {%4,%5,%6,%7}, {%8,%9}, {%0,%1,%2,%3};"
        : "+f"(c[0]), "+f"(c[1]), "+f"(c[2]), "+f"(c[3])
        : "r"(a0), "r"(a1), "r"(a2), "r"(a3), "r"(b0), "r"(b1));
}

// ---------------- setup kernels ----------------
__global__ void zero_kernel() {
    int i = blockIdx.x * blockDim.x + threadIdx.x;
    if (i < N_NODES) g_degi[i] = 0;
    if (i < NG * D)  g_pooled[i] = 0.0f;
    if (i < NG)      g_cnt[i] = 0.0f;
}

__global__ void deg_kernel(const int* __restrict__ dst) {
    int i = blockIdx.x * blockDim.x + threadIdx.x;
    if (i >= ETOT) return;
    int d = (i < N_EDGES) ? dst[i] : (i - N_EDGES);
    atomicAdd(&g_degi[d], 1);
}

__global__ void deg_fin_kernel(const int* __restrict__ batch) {
    int i = blockIdx.x * blockDim.x + threadIdx.x;
    if (i >= N_NODES) return;
    g_dinv[i] = rsqrtf(fmaxf((float)g_degi[i], 1.0f));
    atomicAdd(&g_cnt[batch[i]], 1.0f);
}

// single-pass exclusive scan: each thread owns 20 consecutive elements in registers
#define SCAN_PER 20   // 1024 * 20 = 20480 >= N_NODES
__global__ void scan_kernel() {
    __shared__ int wsum[32];
    int t = threadIdx.x, lane = t & 31, wid = t >> 5;
    int base = t * SCAN_PER;
    int loc[SCAN_PER];
    int sum = 0;
#pragma unroll
    for (int j = 0; j < SCAN_PER; j++) {
        int i = base + j;
        int v = (i < N_NODES) ? g_degi[i] : 0;
        loc[j] = v;
        sum += v;
    }
    // warp inclusive scan of per-thread sums
    int incl = sum;
#pragma unroll
    for (int o = 1; o < 32; o <<= 1) {
        int n = __shfl_up_sync(0xFFFFFFFFu, incl, o);
        if (lane >= o) incl += n;
    }
    if (lane == 31) wsum[wid] = incl;
    __syncthreads();
    if (wid == 0) {
        int w = wsum[lane];
        int wi = w;
#pragma unroll
        for (int o = 1; o < 32; o <<= 1) {
            int n = __shfl_up_sync(0xFFFFFFFFu, wi, o);
            if (lane >= o) wi += n;
        }
        wsum[lane] = wi - w;   // exclusive warp offsets
    }
    __syncthreads();
    int run = wsum[wid] + incl - sum;   // exclusive prefix for this thread's segment
#pragma unroll
    for (int j = 0; j < SCAN_PER; j++) {
        int i = base + j;
        if (i < N_NODES) { g_rowptr[i] = run; g_cursor[i] = run; }
        run += loc[j];
    }
    if (t == 1023) g_rowptr[N_NODES] = run;
}

__global__ void scatter_kernel(const int* __restrict__ src, const int* __restrict__ dst) {
    int i = blockIdx.x * blockDim.x + threadIdx.x;
    if (i >= ETOT) return;
    int s = (i < N_EDGES) ? src[i] : (i - N_EDGES);
    int d = (i < N_EDGES) ? dst[i] : (i - N_EDGES);
    int pos = atomicAdd(&g_cursor[d], 1);
    g_esrc[pos] = s;
}

// ---------------- GEMM v6b: 3xTF32 mma, lane-ordered fragment-major B, A from gmem ----------
// Block: 128 rows x 64 cols, 8 warps (16 rows x 64 cols each), K=128.
// grid = (157, 2, 3): x = row block, y = column half, z = matrix (gat/gcn/lin).
// mat==0 epilogue plain-stores partial es/ed into g_esp/g_edp[half*N + row].
// mat==1 epilogue scales rows by dinv[row] (GCN norm source side folded in).
#define NTB 8                               // n-tiles per block (64 cols)
#define BFRAG_BYTES (NTB * 16 * 32 * 16)    // 65536
#define SMEM_TOTAL_G (BFRAG_BYTES + 3 * 64 * 4)

__global__ void __launch_bounds__(256, 3)
gemm6(const float* __restrict__ x, int insel, int relu,
      const float* __restrict__ gatW, const float* __restrict__ gcnW,
      const float* __restrict__ linW,
      const float* __restrict__ gat_b, const float* __restrict__ gcn_b,
      const float* __restrict__ lin_b,
      const float* __restrict__ a0v, const float* __restrict__ a1v,
      int outsel) {
    extern __shared__ char smraw[];
    float4* Bf4   = (float4*)smraw;
    float*  biasS = (float*)(smraw + BFRAG_BYTES);   // 64
    float*  a0S   = biasS + 64;                      // 64
    float*  a1S   = a0S + 64;                        // 64

    const float* hin = (insel == 0) ? x : ((insel == 1) ? g_bufA : g_bufB);
    int mat = blockIdx.z;
    const float* W = (mat == 0) ? gatW : ((mat == 1) ? gcnW : linW);
    float* out = (mat == 0) ? g_hg : ((mat == 1) ? g_hc : (outsel ? g_bufB : g_bufA));

    int row0 = blockIdx.x * 128;
    int half = blockIdx.y;
    int col0 = half * 64;
    int tid = threadIdx.x;
    int warp = tid >> 5;
    int lane = tid & 31;
    int gid = lane >> 2;
    int tig = lane & 3;

    for (int it = 0; it < 16; it++) {
        int f = warp * 16 + it;
        int nt = f >> 4, kt = f & 15;
        int k = kt * 8 + tig;
        int n = col0 + nt * 8 + gid;
        float w0 = W[k * D + n];
        float w1 = W[(k + 4) * D + n];
        unsigned h0 = f2tf32(w0);
        unsigned l0 = f2tf32(w0 - __uint_as_float(h0));
        unsigned h1 = f2tf32(w1);
        unsigned l1 = f2tf32(w1 - __uint_as_float(h1));
        Bf4[f * 32 + lane] = make_float4(__uint_as_float(h0), __uint_as_float(l0),
                                         __uint_as_float(h1), __uint_as_float(l1));
    }
    if (tid < 64) {
        int c = col0 + tid;
        biasS[tid] = (mat == 2) ? (lin_b[c] + gat_b[c] + gcn_b[c]) : 0.f;
        if (mat == 0) { a0S[tid] = a0v[c]; a1S[tid] = a1v[c]; }
    }
    __syncthreads();

    int mrow0 = warp * 16;
    int rA = row0 + mrow0 + gid;
    int rB = rA + 8;
    bool okA = rA < N_NODES, okB = rB < N_NODES;

    float acc[NTB][4];
#pragma unroll
    for (int nt = 0; nt < NTB; nt++)
#pragma unroll
        for (int j = 0; j < 4; j++) acc[nt][j] = 0.f;

#pragma unroll 2
    for (int kt = 0; kt < 16; kt++) {
        int k0 = kt * 8;
        float av[4];
        av[0] = okA ? hin[(size_t)rA * D + k0 + tig] : 0.f;
        av[1] = okB ? hin[(size_t)rB * D + k0 + tig] : 0.f;
        av[2] = okA ? hin[(size_t)rA * D + k0 + tig + 4] : 0.f;
        av[3] = okB ? hin[(size_t)rB * D + k0 + tig + 4] : 0.f;
        unsigned ah[4], al[4];
#pragma unroll
        for (int j = 0; j < 4; j++) {
            float a = relu ? fmaxf(av[j], 0.f) : av[j];
            ah[j] = f2tf32(a);
            al[j] = f2tf32(a - __uint_as_float(ah[j]));
        }
#pragma unroll
        for (int nt = 0; nt < NTB; nt++) {
            float4 b = Bf4[(nt * 16 + kt) * 32 + lane];   // conflict-free LDS.128
            unsigned bh0 = __float_as_uint(b.x), bl0 = __float_as_uint(b.y);
            unsigned bh1 = __float_as_uint(b.z), bl1 = __float_as_uint(b.w);
            mma_tf32(acc[nt], ah[0], ah[1], ah[2], ah[3], bh0, bh1);
            mma_tf32(acc[nt], ah[0], ah[1], ah[2], ah[3], bl0, bl1);
            mma_tf32(acc[nt], al[0], al[1], al[2], al[3], bh0, bh1);
        }
    }

    // ---- epilogue: bias (+ dinv scale for gcn) + store.
    // C layout: c0,c1 -> (row gid, cols 2tig, 2tig+1); c2,c3 -> (row gid+8). ----
    float sA = 1.f, sB = 1.f;
    if (mat == 1) {
        sA = okA ? g_dinv[rA] : 0.f;
        sB = okB ? g_dinv[rB] : 0.f;
    }
#pragma unroll
    for (int nt = 0; nt < NTB; nt++) {
        int lc = nt * 8 + tig * 2;
        int col = col0 + lc;
        float b0 = biasS[lc], b1 = biasS[lc + 1];
        if (okA)
            *(float2*)&out[(size_t)rA * D + col] =
                make_float2((acc[nt][0] + b0) * sA, (acc[nt][1] + b1) * sA);
        if (okB)
            *(float2*)&out[(size_t)rB * D + col] =
                make_float2((acc[nt][2] + b0) * sB, (acc[nt][3] + b1) * sB);
    }

    if (mat == 0) {
        float esA = 0.f, edA = 0.f, esB = 0.f, edB = 0.f;
#pragma unroll
        for (int nt = 0; nt < NTB; nt++) {
            int lc = nt * 8 + tig * 2;
            float p0 = a0S[lc], p1 = a0S[lc + 1];
            float q0 = a1S[lc], q1 = a1S[lc + 1];
            esA += acc[nt][0] * p0 + acc[nt][1] * p1;
            edA += acc[nt][0] * q0 + acc[nt][1] * q1;
            esB += acc[nt][2] * p0 + acc[nt][3] * p1;
            edB += acc[nt][2] * q0 + acc[nt][3] * q1;
        }
#pragma unroll
        for (int o = 1; o < 4; o <<= 1) {
            esA += __shfl_xor_sync(0xFFFFFFFFu, esA, o);
            edA += __shfl_xor_sync(0xFFFFFFFFu, edA, o);
            esB += __shfl_xor_sync(0xFFFFFFFFu, esB, o);
            edB += __shfl_xor_sync(0xFFFFFFFFu, edB, o);
        }
        if (tig == 0) {
            int ofs = half * N_NODES;
            if (okA) { g_esp[ofs + rA] = esA; g_edp[ofs + rA] = edA; }
            if (okB) { g_esp[ofs + rB] = esB; g_edp[ofs + rB] = edB; }
        }
    }
}

// ---------------- fused CSR edge gather: softmax denom + message accumulate ----------------
// One warp per destination node. hc already carries dinv[s]; dinv[d] applied once at the end.
__global__ void __launch_bounds__(256, 8)
edge_gather(int outsel) {
    int d = (blockIdx.x * blockDim.x + threadIdx.x) >> 5;
    int lane = threadIdx.x & 31;
    if (d >= N_NODES) return;
    float* hnew = outsel ? g_bufB : g_bufA;

    int beg = g_rowptr[d];
    int end = g_rowptr[d + 1];
    float edd = g_edp[d] + g_edp[N_NODES + d];
    float dinvd = g_dinv[d];

    // pass 1: softmax denominator (lane-parallel over edges)
    float sum = 0.f;
    for (int j = beg + lane; j < end; j += 32) {
        int s = g_esrc[j];
        float e = g_esp[s] + g_esp[N_NODES + s] + edd;
        e = (e >= 0.f) ? e : 0.2f * e;
        sum += __expf(e);
    }
#pragma unroll
    for (int o = 16; o > 0; o >>= 1) sum += __shfl_xor_sync(0xFFFFFFFFu, sum, o);
    float inv_denom = 1.0f / sum;   // deg >= 1 (self-loop) so sum > 0

    // pass 2: accumulate messages (warp-cooperative per edge, lanes split D)
    float4 ag = make_float4(0.f, 0.f, 0.f, 0.f);   // GAT
    float4 ac = make_float4(0.f, 0.f, 0.f, 0.f);   // GCN (pre-dinv[d])
    for (int j = beg; j < end; j++) {
        int s = g_esrc[j];                          // uniform across warp -> broadcast
        float e = g_esp[s] + g_esp[N_NODES + s] + edd;
        e = (e >= 0.f) ? e : 0.2f * e;
        float alpha = __expf(e) * inv_denom;
        float4 vg = *(const float4*)&g_hg[(size_t)s * D + lane * 4];
        float4 vc = *(const float4*)&g_hc[(size_t)s * D + lane * 4];
        ag.x += alpha * vg.x; ag.y += alpha * vg.y;
        ag.z += alpha * vg.z; ag.w += alpha * vg.w;
        ac.x += vc.x; ac.y += vc.y; ac.z += vc.z; ac.w += vc.w;
    }
    float4 base = *(const float4*)&hnew[(size_t)d * D + lane * 4];
    base.x += ag.x + dinvd * ac.x;
    base.y += ag.y + dinvd * ac.y;
    base.z += ag.z + dinvd * ac.z;
    base.w += ag.w + dinvd * ac.w;
    *(float4*)&hnew[(size_t)d * D + lane * 4] = base;
}

// ---------------- pooling ----------------
__global__ void pool_kernel(const int* __restrict__ batch) {
    int w = (blockIdx.x * blockDim.x + threadIdx.x) >> 5;
    int lane = threadIdx.x & 31;
    int n0 = w * 8;
    if (n0 >= N_NODES) return;
    float4 acc = make_float4(0.f, 0.f, 0.f, 0.f);
    int curg = batch[n0];
    for (int j = 0; j < 8; j++) {
        int n = n0 + j;
        if (n >= N_NODES) break;
        int g = batch[n];
        if (g != curg) {
            atomicAdd((float4*)&g_pooled[(size_t)curg * D + lane * 4], acc);
            acc = make_float4(0.f, 0.f, 0.f, 0.f);
            curg = g;
        }
        float4 v = *(const float4*)&g_bufA[(size_t)n * D + lane * 4];
        acc.x += v.x; acc.y += v.y; acc.z += v.z; acc.w += v.w;
    }
    atomicAdd((float4*)&g_pooled[(size_t)curg * D + lane * 4], acc);
}

__global__ void final_kernel(const float* __restrict__ lin4W, const float* __restrict__ lin4b,
                             float* __restrict__ out) {
    int t = threadIdx.x;
    if (t < NG * 2) {
        int g = t >> 1, o = t & 1;
        float inv = 1.0f / fmaxf(g_cnt[g], 1.0f);
        float sum = 0.f;
        for (int k = 0; k < D; k++) sum += g_pooled[g * D + k] * lin4W[k * 2 + o];
        out[t] = sum * inv + lin4b[o];
    }
}

// ---------------- launch ----------------
extern "C" void kernel_launch(void* const* d_in, const int* in_sizes, int n_in,
                              void* d_out, int out_size) {
    const float* x     = (const float*)d_in[0];
    const float* gatW  = (const float*)d_in[1];
    const float* gata  = (const float*)d_in[2];
    const float* gatb  = (const float*)d_in[3];
    const float* gcnW  = (const float*)d_in[4];
    const float* gcnb  = (const float*)d_in[5];
    const float* linW  = (const float*)d_in[6];
    const float* linb  = (const float*)d_in[7];
    const float* lin4W = (const float*)d_in[8];
    const float* lin4b = (const float*)d_in[9];
    const int*   src   = (const int*)d_in[10];
    const int*   dst   = (const int*)d_in[11];
    const int*   batch = (const int*)d_in[12];
    float* out = (float*)d_out;
    (void)in_sizes; (void)n_in; (void)out_size;

    cudaFuncSetAttribute(gemm6, cudaFuncAttributeMaxDynamicSharedMemorySize, SMEM_TOTAL_G);

    // one-time CSR build + degree norms
    zero_kernel<<<(N_NODES + 255) / 256, 256>>>();
    deg_kernel<<<(ETOT + 255) / 256, 256>>>(dst);
    deg_fin_kernel<<<(N_NODES + 255) / 256, 256>>>(batch);
    scan_kernel<<<1, 1024>>>();
    scatter_kernel<<<(ETOT + 255) / 256, 256>>>(src, dst);

    for (int i = 0; i < 3; i++) {
        int insel  = (i == 0) ? 0 : ((i == 1) ? 1 : 2);   // x, bufA, bufB
        int outsel = (i == 1) ? 1 : 0;                    // bufA, bufB, bufA
        int relu   = (i > 0) ? 1 : 0;

        dim3 grid((N_NODES + 127) / 128, 2, 3);
        gemm6<<<grid, 256, SMEM_TOTAL_G>>>(x, insel, relu,
                                           gatW + i * D * D, gcnW + i * D * D, linW + i * D * D,
                                           gatb + i * D, gcnb + i * D, linb + i * D,
                                           gata + i * 2 * D, gata + i * 2 * D + D, outsel);

        edge_gather<<<(N_NODES * 32 + 255) / 256, 256>>>(outsel);
    }

    pool_kernel<<<((N_NODES / 8) * 32 + 255) / 256, 256>>>(batch);
    final_kernel<<<1, 128>>>(lin4W, lin4b, out);
}

// round 15
// speedup vs baseline: 1.1882x; 1.1882x over previous
#include <cuda_runtime.h>
#include <cuda_bf16.h>
#include <math.h>

#define N_NODES 20000
#define N_EDGES 320000
#define D 128
#define ETOT (N_EDGES + N_NODES)   // edges + self-loops = 340000
#define NG 64

// ---------------- scratch (device globals; no allocation allowed) ----------------
__device__ float g_bufA[N_NODES * D];
__device__ float g_bufB[N_NODES * D];
__device__ float g_hg[N_NODES * D];     // h @ gat_W
__device__ float g_hc[N_NODES * D];     // dinv[s] * (h @ gcn_W)   (dinv folded in)
__device__ float g_esp[2 * N_NODES];    // partial hg.a_src per column-half (plain stores)
__device__ float g_edp[2 * N_NODES];    // partial hg.a_dst per column-half
__device__ float g_dinv[N_NODES];       // deg^-1/2
__device__ float g_pooled[NG * D];
__device__ float g_cnt[NG];
// CSR (built once per launch; dst-grouped)
__device__ int g_degi[N_NODES];
__device__ int g_rowptr[N_NODES + 1];
__device__ int g_cursor[N_NODES];
__device__ int g_esrc[ETOT];            // src node per CSR slot (grouped by dst)

// ---------------- helpers ----------------
__device__ __forceinline__ unsigned bf2_bits(__nv_bfloat162 v) {
    return *(unsigned*)&v;
}

// split (x, y) floats into packed bf16x2 hi and lo (residual) words; x in low half
__device__ __forceinline__ void bfsplit2(float x, float y, unsigned& hi, unsigned& lo) {
    __nv_bfloat162 h = __floats2bfloat162_rn(x, y);
    float rx = x - __low2float(h);
    float ry = y - __high2float(h);
    __nv_bfloat162 l = __floats2bfloat162_rn(rx, ry);
    hi = bf2_bits(h);
    lo = bf2_bits(l);
}

__device__ __forceinline__ void mma_bf16(float* c, unsigned a0, unsigned a1, unsigned a2,
                                         unsigned a3, unsigned b0, unsigned b1) {
    asm volatile(
        "mma.sync.aligned.m16n8k16.row.col.f32.bf16.bf16.f32 "
        "{%0,%1,%2,%3}, {%4,%5,%6,%7}, {%8,%9}, {%0,%1,%2,%3};"
        : "+f"(c[0]), "+f"(c[1]), "+f"(c[2]), "+f"(c[3])
        : "r"(a0), "r"(a1), "r"(a2), "r"(a3), "r"(b0), "r"(b1));
}

// ---------------- setup kernels ----------------
__global__ void zero_kernel() {
    int i = blockIdx.x * blockDim.x + threadIdx.x;
    if (i < N_NODES) g_degi[i] = 0;
    if (i < NG * D)  g_pooled[i] = 0.0f;
    if (i < NG)      g_cnt[i] = 0.0f;
}

__global__ void deg_kernel(const int* __restrict__ dst) {
    int i = blockIdx.x * blockDim.x + threadIdx.x;
    if (i >= ETOT) return;
    int d = (i < N_EDGES) ? dst[i] : (i - N_EDGES);
    atomicAdd(&g_degi[d], 1);
}

__global__ void deg_fin_kernel(const int* __restrict__ batch) {
    int i = blockIdx.x * blockDim.x + threadIdx.x;
    if (i >= N_NODES) return;
    g_dinv[i] = rsqrtf(fmaxf((float)g_degi[i], 1.0f));
    atomicAdd(&g_cnt[batch[i]], 1.0f);
}

// single-pass exclusive scan via smem staging:
// coalesced copy g_degi -> smem, then each thread scans 20 consecutive smem ints.
#define SCAN_PER 20                       // 1024 * 20 = 20480 >= N_NODES
#define SCAN_TOT (1024 * SCAN_PER)
#define SCAN_SMEM (SCAN_TOT * 4)          // 81920 B dynamic smem
__global__ void scan_kernel() {
    extern __shared__ int sdeg[];
    __shared__ int wsum[32];
    int t = threadIdx.x, lane = t & 31, wid = t >> 5;
    for (int i = t; i < SCAN_TOT; i += 1024)
        sdeg[i] = (i < N_NODES) ? g_degi[i] : 0;
    __syncthreads();
    int base = t * SCAN_PER;
    int sum = 0;
#pragma unroll
    for (int j = 0; j < SCAN_PER; j++) sum += sdeg[base + j];
    // warp inclusive scan of per-thread sums
    int incl = sum;
#pragma unroll
    for (int o = 1; o < 32; o <<= 1) {
        int n = __shfl_up_sync(0xFFFFFFFFu, incl, o);
        if (lane >= o) incl += n;
    }
    if (lane == 31) wsum[wid] = incl;
    __syncthreads();
    if (wid == 0) {
        int w = wsum[lane];
        int wi = w;
#pragma unroll
        for (int o = 1; o < 32; o <<= 1) {
            int n = __shfl_up_sync(0xFFFFFFFFu, wi, o);
            if (lane >= o) wi += n;
        }
        wsum[lane] = wi - w;   // exclusive warp offsets
    }
    __syncthreads();
    int run = wsum[wid] + incl - sum;   // exclusive prefix for this thread's segment
#pragma unroll
    for (int j = 0; j < SCAN_PER; j++) {
        int i = base + j;
        if (i < N_NODES) { g_rowptr[i] = run; g_cursor[i] = run; }
        run += sdeg[base + j];
    }
    if (t == 1023) g_rowptr[N_NODES] = run;
}

__global__ void scatter_kernel(const int* __restrict__ src, const int* __restrict__ dst) {
    int i = blockIdx.x * blockDim.x + threadIdx.x;
    if (i >= ETOT) return;
    int s = (i < N_EDGES) ? src[i] : (i - N_EDGES);
    int d = (i < N_EDGES) ? dst[i] : (i - N_EDGES);
    int pos = atomicAdd(&g_cursor[d], 1);
    g_esrc[pos] = s;
}

// ---------------- GEMM v7: 2-term bf16 mma (m16n8k16), fragment-major B, A from gmem ----
// Block: 128 rows x 64 cols, 8 warps (16 rows x 64 cols each), K=128 (8 k-tiles of 16).
// grid = (157, 2, 3): x = row block, y = column half, z = matrix (gat/gcn/lin).
// D = Ah*Bh + Ah*Bl + Al*Bh  (bf16 hi/lo split; dropped Al*Bl ~2^-16 rel, incoherent sum).
// smem fragment payload per lane: float4 = (bh0, bh1, bl0, bl1) bit-packed bf16x2 words.
// mat==0 epilogue stores partial es/ed; mat==1 epilogue scales rows by dinv[row].
#define NTB 8                               // n-tiles per block (64 cols)
#define KTB 8                               // k-tiles (K=128 / 16)
#define BFRAG_BYTES (NTB * KTB * 32 * 16)   // 32768
#define SMEM_TOTAL_G (BFRAG_BYTES + 3 * 64 * 4)

__global__ void __launch_bounds__(256, 3)
gemm7(const float* __restrict__ x, int insel, int relu,
      const float* __restrict__ gatW, const float* __restrict__ gcnW,
      const float* __restrict__ linW,
      const float* __restrict__ gat_b, const float* __restrict__ gcn_b,
      const float* __restrict__ lin_b,
      const float* __restrict__ a0v, const float* __restrict__ a1v,
      int outsel) {
    extern __shared__ char smraw[];
    float4* Bf4   = (float4*)smraw;
    float*  biasS = (float*)(smraw + BFRAG_BYTES);   // 64
    float*  a0S   = biasS + 64;                      // 64
    float*  a1S   = a0S + 64;                        // 64

    const float* hin = (insel == 0) ? x : ((insel == 1) ? g_bufA : g_bufB);
    int mat = blockIdx.z;
    const float* W = (mat == 0) ? gatW : ((mat == 1) ? gcnW : linW);
    float* out = (mat == 0) ? g_hg : ((mat == 1) ? g_hc : (outsel ? g_bufB : g_bufA));

    int row0 = blockIdx.x * 128;
    int half = blockIdx.y;
    int col0 = half * 64;
    int tid = threadIdx.x;
    int warp = tid >> 5;
    int lane = tid & 31;
    int gid = lane >> 2;   // 0..7
    int tig = lane & 3;    // 0..3

    // ---- prologue: load W half, bf16 hi/lo split, store fragment-major ----
    // fragment f = nt*KTB + kt; lane holds col n = col0 + nt*8 + gid,
    // k rows: b0 <- (k0+2tig, k0+2tig+1), b1 <- (k0+8+2tig, k0+8+2tig+1), k0 = kt*16.
    for (int it = 0; it < 8; it++) {
        int f = warp * 8 + it;
        int nt = f >> 3, kt = f & 7;
        int k0 = kt * 16;
        int n = col0 + nt * 8 + gid;
        float w00 = W[(k0 + 2 * tig) * D + n];
        float w01 = W[(k0 + 2 * tig + 1) * D + n];
        float w10 = W[(k0 + 8 + 2 * tig) * D + n];
        float w11 = W[(k0 + 8 + 2 * tig + 1) * D + n];
        unsigned bh0, bl0, bh1, bl1;
        bfsplit2(w00, w01, bh0, bl0);
        bfsplit2(w10, w11, bh1, bl1);
        Bf4[f * 32 + lane] = make_float4(__uint_as_float(bh0), __uint_as_float(bh1),
                                         __uint_as_float(bl0), __uint_as_float(bl1));
    }
    if (tid < 64) {
        int c = col0 + tid;
        biasS[tid] = (mat == 2) ? (lin_b[c] + gat_b[c] + gcn_b[c]) : 0.f;
        if (mat == 0) { a0S[tid] = a0v[c]; a1S[tid] = a1v[c]; }
    }
    __syncthreads();

    int mrow0 = warp * 16;
    int rA = row0 + mrow0 + gid;
    int rB = rA + 8;
    bool okA = rA < N_NODES, okB = rB < N_NODES;

    float acc[NTB][4];
#pragma unroll
    for (int nt = 0; nt < NTB; nt++)
#pragma unroll
        for (int j = 0; j < 4; j++) acc[nt][j] = 0.f;

#pragma unroll 2
    for (int kt = 0; kt < KTB; kt++) {
        int k0 = kt * 16;
        // A fragments (m16k16): float2 loads (cols 2tig,2tig+1), rows rA/rB, k-halves 0/8
        float2 z = make_float2(0.f, 0.f);
        float2 p0 = okA ? *(const float2*)&hin[(size_t)rA * D + k0 + 2 * tig] : z;
        float2 p1 = okB ? *(const float2*)&hin[(size_t)rB * D + k0 + 2 * tig] : z;
        float2 p2 = okA ? *(const float2*)&hin[(size_t)rA * D + k0 + 8 + 2 * tig] : z;
        float2 p3 = okB ? *(const float2*)&hin[(size_t)rB * D + k0 + 8 + 2 * tig] : z;
        if (relu) {
            p0.x = fmaxf(p0.x, 0.f); p0.y = fmaxf(p0.y, 0.f);
            p1.x = fmaxf(p1.x, 0.f); p1.y = fmaxf(p1.y, 0.f);
            p2.x = fmaxf(p2.x, 0.f); p2.y = fmaxf(p2.y, 0.f);
            p3.x = fmaxf(p3.x, 0.f); p3.y = fmaxf(p3.y, 0.f);
        }
        unsigned ah[4], al[4];
        bfsplit2(p0.x, p0.y, ah[0], al[0]);
        bfsplit2(p1.x, p1.y, ah[1], al[1]);
        bfsplit2(p2.x, p2.y, ah[2], al[2]);
        bfsplit2(p3.x, p3.y, ah[3], al[3]);
#pragma unroll
        for (int nt = 0; nt < NTB; nt++) {
            float4 b = Bf4[(nt * KTB + kt) * 32 + lane];   // conflict-free LDS.128
            unsigned bh0 = __float_as_uint(b.x), bh1 = __float_as_uint(b.y);
            unsigned bl0 = __float_as_uint(b.z), bl1 = __float_as_uint(b.w);
            mma_bf16(acc[nt], ah[0], ah[1], ah[2], ah[3], bh0, bh1);
            mma_bf16(acc[nt], ah[0], ah[1], ah[2], ah[3], bl0, bl1);
            mma_bf16(acc[nt], al[0], al[1], al[2], al[3], bh0, bh1);
        }
    }

    // ---- epilogue: bias (+ dinv scale for gcn) + store.
    // C layout: c0,c1 -> (row gid, cols 2tig, 2tig+1); c2,c3 -> (row gid+8). ----
    float sA = 1.f, sB = 1.f;
    if (mat == 1) {
        sA = okA ? g_dinv[rA] : 0.f;
        sB = okB ? g_dinv[rB] : 0.f;
    }
#pragma unroll
    for (int nt = 0; nt < NTB; nt++) {
        int lc = nt * 8 + tig * 2;
        int col = col0 + lc;
        float b0 = biasS[lc], b1 = biasS[lc + 1];
        if (okA)
            *(float2*)&out[(size_t)rA * D + col] =
                make_float2((acc[nt][0] + b0) * sA, (acc[nt][1] + b1) * sA);
        if (okB)
            *(float2*)&out[(size_t)rB * D + col] =
                make_float2((acc[nt][2] + b0) * sB, (acc[nt][3] + b1) * sB);
    }

    if (mat == 0) {
        float esA = 0.f, edA = 0.f, esB = 0.f, edB = 0.f;
#pragma unroll
        for (int nt = 0; nt < NTB; nt++) {
            int lc = nt * 8 + tig * 2;
            float p0 = a0S[lc], p1 = a0S[lc + 1];
            float q0 = a1S[lc], q1 = a1S[lc + 1];
            esA += acc[nt][0] * p0 + acc[nt][1] * p1;
            edA += acc[nt][0] * q0 + acc[nt][1] * q1;
            esB += acc[nt][2] * p0 + acc[nt][3] * p1;
            edB += acc[nt][2] * q0 + acc[nt][3] * q1;
        }
#pragma unroll
        for (int o = 1; o < 4; o <<= 1) {
            esA += __shfl_xor_sync(0xFFFFFFFFu, esA, o);
            edA += __shfl_xor_sync(0xFFFFFFFFu, edA, o);
            esB += __shfl_xor_sync(0xFFFFFFFFu, esB, o);
            edB += __shfl_xor_sync(0xFFFFFFFFu, edB, o);
        }
        if (tig == 0) {
            int ofs = half * N_NODES;
            if (okA) { g_esp[ofs + rA] = esA; g_edp[ofs + rA] = edA; }
            if (okB) { g_esp[ofs + rB] = esB; g_edp[ofs + rB] = edB; }
        }
    }
}

// ---------------- fused CSR edge gather: softmax denom + message accumulate ----------------
// One warp per destination node. hc already carries dinv[s]; dinv[d] applied once at the end.
__global__ void __launch_bounds__(256, 8)
edge_gather(int outsel) {
    int d = (blockIdx.x * blockDim.x + threadIdx.x) >> 5;
    int lane = threadIdx.x & 31;
    if (d >= N_NODES) return;
    float* hnew = outsel ? g_bufB : g_bufA;

    int beg = g_rowptr[d];
    int end = g_rowptr[d + 1];
    float edd = g_edp[d] + g_edp[N_NODES + d];
    float dinvd = g_dinv[d];

    // pass 1: softmax denominator (lane-parallel over edges)
    float sum = 0.f;
    for (int j = beg + lane; j < end; j += 32) {
        int s = g_esrc[j];
        float e = g_esp[s] + g_esp[N_NODES + s] + edd;
        e = (e >= 0.f) ? e : 0.2f * e;
        sum += __expf(e);
    }
#pragma unroll
    for (int o = 16; o > 0; o >>= 1) sum += __shfl_xor_sync(0xFFFFFFFFu, sum, o);
    float inv_denom = 1.0f / sum;   // deg >= 1 (self-loop) so sum > 0

    // pass 2: accumulate messages (warp-cooperative per edge, lanes split D)
    float4 ag = make_float4(0.f, 0.f, 0.f, 0.f);   // GAT
    float4 ac = make_float4(0.f, 0.f, 0.f, 0.f);   // GCN (pre-dinv[d])
    for (int j = beg; j < end; j++) {
        int s = g_esrc[j];                          // uniform across warp -> broadcast
        float e = g_esp[s] + g_esp[N_NODES + s] + edd;
        e = (e >= 0.f) ? e : 0.2f * e;
        float alpha = __expf(e) * inv_denom;
        float4 vg = *(const float4*)&g_hg[(size_t)s * D + lane * 4];
        float4 vc = *(const float4*)&g_hc[(size_t)s * D + lane * 4];
        ag.x += alpha * vg.x; ag.y += alpha * vg.y;
        ag.z += alpha * vg.z; ag.w += alpha * vg.w;
        ac.x += vc.x; ac.y += vc.y; ac.z += vc.z; ac.w += vc.w;
    }
    float4 base = *(const float4*)&hnew[(size_t)d * D + lane * 4];
    base.x += ag.x + dinvd * ac.x;
    base.y += ag.y + dinvd * ac.y;
    base.z += ag.z + dinvd * ac.z;
    base.w += ag.w + dinvd * ac.w;
    *(float4*)&hnew[(size_t)d * D + lane * 4] = base;
}

// ---------------- pooling ----------------
__global__ void pool_kernel(const int* __restrict__ batch) {
    int w = (blockIdx.x * blockDim.x + threadIdx.x) >> 5;
    int lane = threadIdx.x & 31;
    int n0 = w * 8;
    if (n0 >= N_NODES) return;
    float4 acc = make_float4(0.f, 0.f, 0.f, 0.f);
    int curg = batch[n0];
    for (int j = 0; j < 8; j++) {
        int n = n0 + j;
        if (n >= N_NODES) break;
        int g = batch[n];
        if (g != curg) {
            atomicAdd((float4*)&g_pooled[(size_t)curg * D + lane * 4], acc);
            acc = make_float4(0.f, 0.f, 0.f, 0.f);
            curg = g;
        }
        float4 v = *(const float4*)&g_bufA[(size_t)n * D + lane * 4];
        acc.x += v.x; acc.y += v.y; acc.z += v.z; acc.w += v.w;
    }
    atomicAdd((float4*)&g_pooled[(size_t)curg * D + lane * 4], acc);
}

__global__ void final_kernel(const float* __restrict__ lin4W, const float* __restrict__ lin4b,
                             float* __restrict__ out) {
    int t = threadIdx.x;
    if (t < NG * 2) {
        int g = t >> 1, o = t & 1;
        float inv = 1.0f / fmaxf(g_cnt[g], 1.0f);
        float sum = 0.f;
        for (int k = 0; k < D; k++) sum += g_pooled[g * D + k] * lin4W[k * 2 + o];
        out[t] = sum * inv + lin4b[o];
    }
}

// ---------------- launch ----------------
extern "C" void kernel_launch(void* const* d_in, const int* in_sizes, int n_in,
                              void* d_out, int out_size) {
    const float* x     = (const float*)d_in[0];
    const float* gatW  = (const float*)d_in[1];
    const float* gata  = (const float*)d_in[2];
    const float* gatb  = (const float*)d_in[3];
    const float* gcnW  = (const float*)d_in[4];
    const float* gcnb  = (const float*)d_in[5];
    const float* linW  = (const float*)d_in[6];
    const float* linb  = (const float*)d_in[7];
    const float* lin4W = (const float*)d_in[8];
    const float* lin4b = (const float*)d_in[9];
    const int*   src   = (const int*)d_in[10];
    const int*   dst   = (const int*)d_in[11];
    const int*   batch = (const int*)d_in[12];
    float* out = (float*)d_out;
    (void)in_sizes; (void)n_in; (void)out_size;

    cudaFuncSetAttribute(gemm7, cudaFuncAttributeMaxDynamicSharedMemorySize, SMEM_TOTAL_G);
    cudaFuncSetAttribute(scan_kernel, cudaFuncAttributeMaxDynamicSharedMemorySize, SCAN_SMEM);

    // one-time CSR build + degree norms
    zero_kernel<<<(N_NODES + 255) / 256, 256>>>();
    deg_kernel<<<(ETOT + 255) / 256, 256>>>(dst);
    deg_fin_kernel<<<(N_NODES + 255) / 256, 256>>>(batch);
    scan_kernel<<<1, 1024, SCAN_SMEM>>>();
    scatter_kernel<<<(ETOT + 255) / 256, 256>>>(src, dst);

    for (int i = 0; i < 3; i++) {
        int insel  = (i == 0) ? 0 : ((i == 1) ? 1 : 2);   // x, bufA, bufB
        int outsel = (i == 1) ? 1 : 0;                    // bufA, bufB, bufA
        int relu   = (i > 0) ? 1 : 0;

        dim3 grid((N_NODES + 127) / 128, 2, 3);
        gemm7<<<grid, 256, SMEM_TOTAL_G>>>(x, insel, relu,
                                           gatW + i * D * D, gcnW + i * D * D, linW + i * D * D,
                                           gatb + i * D, gcnb + i * D, linb + i * D,
                                           gata + i * 2 * D, gata + i * 2 * D + D, outsel);

        edge_gather<<<(N_NODES * 32 + 255) / 256, 256>>>(outsel);
    }

    pool_kernel<<<((N_NODES / 8) * 32 + 255) / 256, 256>>>(batch);
    final_kernel<<<1, 128>>>(lin4W, lin4b, out);
}

// round 16
// speedup vs baseline: 1.3685x; 1.1517x over previous
#include <cuda_runtime.h>
#include <cuda_bf16.h>
#include <cuda_fp16.h>
#include <math.h>

#define N_NODES 20000
#define N_EDGES 320000
#define D 128
#define ETOT (N_EDGES + N_NODES)   // edges + self-loops = 340000
#define NG 64
#define SCAN_BLOCKS 20              // 20 * 1024 = 20480 >= N_NODES

// ---------------- scratch (device globals; no allocation allowed) ----------------
__device__ float  g_bufA[N_NODES * D];
__device__ float  g_bufB[N_NODES * D];
__device__ __half g_hg[N_NODES * D];    // h @ gat_W              (fp16 storage)
__device__ __half g_hc[N_NODES * D];    // dinv[s]*(h @ gcn_W)    (fp16 storage)
__device__ float  g_esp[2 * N_NODES];   // partial hg.a_src per column-half (fp32, plain stores)
__device__ float  g_edp[2 * N_NODES];   // partial hg.a_dst per column-half
__device__ float  g_dinv[N_NODES];      // deg^-1/2
__device__ float  g_pooled[NG * D];
__device__ float  g_cnt[NG];
// CSR (built once per launch; dst-grouped)
__device__ int g_degi[N_NODES];
__device__ int g_rowptr[N_NODES + 1];
__device__ int g_cursor[N_NODES];
__device__ int g_esrc[ETOT];
__device__ int g_bsum[SCAN_BLOCKS];
__device__ int g_boff[SCAN_BLOCKS];

// ---------------- helpers ----------------
__device__ __forceinline__ unsigned bf2_bits(__nv_bfloat162 v) {
    return *(unsigned*)&v;
}

__device__ __forceinline__ void bfsplit2(float x, float y, unsigned& hi, unsigned& lo) {
    __nv_bfloat162 h = __floats2bfloat162_rn(x, y);
    float rx = x - __low2float(h);
    float ry = y - __high2float(h);
    __nv_bfloat162 l = __floats2bfloat162_rn(rx, ry);
    hi = bf2_bits(h);
    lo = bf2_bits(l);
}

__device__ __forceinline__ void mma_bf16(float* c, unsigned a0, unsigned a1, unsigned a2,
                                         unsigned a3, unsigned b0, unsigned b1) {
    asm volatile(
        "mma.sync.aligned.m16n8k16.row.col.f32.bf16.bf16.f32 "
        "{%0,%1,%2,%3}, {%4,%5,%6,%7}, {%8,%9}, {%0,%1,%2,%3};"
        : "+f"(c[0]), "+f"(c[1]), "+f"(c[2]), "+f"(c[3])
        : "r"(a0), "r"(a1), "r"(a2), "r"(a3), "r"(b0), "r"(b1));
}

// load 4 consecutive halves as float4
__device__ __forceinline__ float4 ldh4(const __half* p) {
    uint2 r = *(const uint2*)p;
    __half2 h0 = *reinterpret_cast<__half2*>(&r.x);
    __half2 h1 = *reinterpret_cast<__half2*>(&r.y);
    float2 f0 = __half22float2(h0), f1 = __half22float2(h1);
    return make_float4(f0.x, f0.y, f1.x, f1.y);
}

// ---------------- setup kernels ----------------
__global__ void zero_kernel() {
    int i = blockIdx.x * blockDim.x + threadIdx.x;
    if (i < N_NODES) g_degi[i] = 0;
    if (i < NG * D)  g_pooled[i] = 0.0f;
    if (i < NG)      g_cnt[i] = 0.0f;
}

__global__ void deg_kernel(const int* __restrict__ dst) {
    int i = blockIdx.x * blockDim.x + threadIdx.x;
    if (i >= ETOT) return;
    int d = (i < N_EDGES) ? dst[i] : (i - N_EDGES);
    atomicAdd(&g_degi[d], 1);
}

__global__ void deg_fin_kernel(const int* __restrict__ batch) {
    int i = blockIdx.x * blockDim.x + threadIdx.x;
    if (i >= N_NODES) return;
    g_dinv[i] = rsqrtf(fmaxf((float)g_degi[i], 1.0f));
    atomicAdd(&g_cnt[batch[i]], 1.0f);
}

// ---- 3-phase multi-block exclusive scan of g_degi -> g_rowptr ----
__global__ void scanA() {   // grid SCAN_BLOCKS, block 1024: block-local exclusive scan
    __shared__ int wsum[32];
    int b = blockIdx.x, t = threadIdx.x, lane = t & 31, wid = t >> 5;
    int i = b * 1024 + t;
    int v = (i < N_NODES) ? g_degi[i] : 0;
    int incl = v;
#pragma unroll
    for (int o = 1; o < 32; o <<= 1) {
        int n = __shfl_up_sync(0xFFFFFFFFu, incl, o);
        if (lane >= o) incl += n;
    }
    if (lane == 31) wsum[wid] = incl;
    __syncthreads();
    if (wid == 0) {
        int w = wsum[lane];
        int wi = w;
#pragma unroll
        for (int o = 1; o < 32; o <<= 1) {
            int n = __shfl_up_sync(0xFFFFFFFFu, wi, o);
            if (lane >= o) wi += n;
        }
        wsum[lane] = wi - w;
    }
    __syncthreads();
    int excl = wsum[wid] + incl - v;
    if (i < N_NODES) g_rowptr[i] = excl;           // block-local for now
    if (t == 1023) g_bsum[b] = wsum[31] + incl;    // block total
}

__global__ void scanB() {   // 1 warp: scan the block sums
    int t = threadIdx.x;
    int v = (t < SCAN_BLOCKS) ? g_bsum[t] : 0;
    int incl = v;
#pragma unroll
    for (int o = 1; o < 32; o <<= 1) {
        int n = __shfl_up_sync(0xFFFFFFFFu, incl, o);
        if (t >= o) incl += n;
    }
    if (t < SCAN_BLOCKS) g_boff[t] = incl - v;
    if (t == SCAN_BLOCKS - 1) g_rowptr[N_NODES] = incl;
}

__global__ void scanC() {   // add block offsets, init cursor
    int b = blockIdx.x;
    int i = b * 1024 + threadIdx.x;
    if (i < N_NODES) {
        int r = g_rowptr[i] + g_boff[b];
        g_rowptr[i] = r;
        g_cursor[i] = r;
    }
}

__global__ void scatter_kernel(const int* __restrict__ src, const int* __restrict__ dst) {
    int i = blockIdx.x * blockDim.x + threadIdx.x;
    if (i >= ETOT) return;
    int s = (i < N_EDGES) ? src[i] : (i - N_EDGES);
    int d = (i < N_EDGES) ? dst[i] : (i - N_EDGES);
    int pos = atomicAdd(&g_cursor[d], 1);
    g_esrc[pos] = s;
}

// ---------------- GEMM v8: 2-term bf16 mma (m16n8k16), fragment-major B, A from gmem ----
// Block: 128 rows x 64 cols, 8 warps, K=128 (8 k-tiles of 16).
// grid = (157, 2, 3): x = row block, y = column half, z = matrix (gat/gcn/lin).
// D = Ah*Bh + Ah*Bl + Al*Bh.
// mat 0/1 outputs are fp16 (g_hg/g_hc); mat 2 (lin + biases) stays fp32.
// mat==0 epilogue stores partial es/ed (fp32 acc); mat==1 scales rows by dinv[row].
#define NTB 8
#define KTB 8
#define BFRAG_BYTES (NTB * KTB * 32 * 16)   // 32768
#define SMEM_TOTAL_G (BFRAG_BYTES + 3 * 64 * 4)

__global__ void __launch_bounds__(256, 3)
gemm8(const float* __restrict__ x, int insel, int relu,
      const float* __restrict__ gatW, const float* __restrict__ gcnW,
      const float* __restrict__ linW,
      const float* __restrict__ gat_b, const float* __restrict__ gcn_b,
      const float* __restrict__ lin_b,
      const float* __restrict__ a0v, const float* __restrict__ a1v,
      int outsel) {
    extern __shared__ char smraw[];
    float4* Bf4   = (float4*)smraw;
    float*  biasS = (float*)(smraw + BFRAG_BYTES);   // 64
    float*  a0S   = biasS + 64;                      // 64
    float*  a1S   = a0S + 64;                        // 64

    const float* hin = (insel == 0) ? x : ((insel == 1) ? g_bufA : g_bufB);
    int mat = blockIdx.z;
    const float* W = (mat == 0) ? gatW : ((mat == 1) ? gcnW : linW);
    __half* outH = (mat == 0) ? g_hg : g_hc;
    float*  outF = outsel ? g_bufB : g_bufA;

    int row0 = blockIdx.x * 128;
    int half = blockIdx.y;
    int col0 = half * 64;
    int tid = threadIdx.x;
    int warp = tid >> 5;
    int lane = tid & 31;
    int gid = lane >> 2;   // 0..7
    int tig = lane & 3;    // 0..3

    // ---- prologue: load W half, bf16 hi/lo split, store fragment-major ----
    for (int it = 0; it < 8; it++) {
        int f = warp * 8 + it;
        int nt = f >> 3, kt = f & 7;
        int k0 = kt * 16;
        int n = col0 + nt * 8 + gid;
        float w00 = W[(k0 + 2 * tig) * D + n];
        float w01 = W[(k0 + 2 * tig + 1) * D + n];
        float w10 = W[(k0 + 8 + 2 * tig) * D + n];
        float w11 = W[(k0 + 8 + 2 * tig + 1) * D + n];
        unsigned bh0, bl0, bh1, bl1;
        bfsplit2(w00, w01, bh0, bl0);
        bfsplit2(w10, w11, bh1, bl1);
        Bf4[f * 32 + lane] = make_float4(__uint_as_float(bh0), __uint_as_float(bh1),
                                         __uint_as_float(bl0), __uint_as_float(bl1));
    }
    if (tid < 64) {
        int c = col0 + tid;
        biasS[tid] = (mat == 2) ? (lin_b[c] + gat_b[c] + gcn_b[c]) : 0.f;
        if (mat == 0) { a0S[tid] = a0v[c]; a1S[tid] = a1v[c]; }
    }
    __syncthreads();

    int mrow0 = warp * 16;
    int rA = row0 + mrow0 + gid;
    int rB = rA + 8;
    bool okA = rA < N_NODES, okB = rB < N_NODES;

    float acc[NTB][4];
#pragma unroll
    for (int nt = 0; nt < NTB; nt++)
#pragma unroll
        for (int j = 0; j < 4; j++) acc[nt][j] = 0.f;

#pragma unroll 2
    for (int kt = 0; kt < KTB; kt++) {
        int k0 = kt * 16;
        float2 z = make_float2(0.f, 0.f);
        float2 p0 = okA ? *(const float2*)&hin[(size_t)rA * D + k0 + 2 * tig] : z;
        float2 p1 = okB ? *(const float2*)&hin[(size_t)rB * D + k0 + 2 * tig] : z;
        float2 p2 = okA ? *(const float2*)&hin[(size_t)rA * D + k0 + 8 + 2 * tig] : z;
        float2 p3 = okB ? *(const float2*)&hin[(size_t)rB * D + k0 + 8 + 2 * tig] : z;
        if (relu) {
            p0.x = fmaxf(p0.x, 0.f); p0.y = fmaxf(p0.y, 0.f);
            p1.x = fmaxf(p1.x, 0.f); p1.y = fmaxf(p1.y, 0.f);
            p2.x = fmaxf(p2.x, 0.f); p2.y = fmaxf(p2.y, 0.f);
            p3.x = fmaxf(p3.x, 0.f); p3.y = fmaxf(p3.y, 0.f);
        }
        unsigned ah[4], al[4];
        bfsplit2(p0.x, p0.y, ah[0], al[0]);
        bfsplit2(p1.x, p1.y, ah[1], al[1]);
        bfsplit2(p2.x, p2.y, ah[2], al[2]);
        bfsplit2(p3.x, p3.y, ah[3], al[3]);
#pragma unroll
        for (int nt = 0; nt < NTB; nt++) {
            float4 b = Bf4[(nt * KTB + kt) * 32 + lane];
            unsigned bh0 = __float_as_uint(b.x), bh1 = __float_as_uint(b.y);
            unsigned bl0 = __float_as_uint(b.z), bl1 = __float_as_uint(b.w);
            mma_bf16(acc[nt], ah[0], ah[1], ah[2], ah[3], bh0, bh1);
            mma_bf16(acc[nt], ah[0], ah[1], ah[2], ah[3], bl0, bl1);
            mma_bf16(acc[nt], al[0], al[1], al[2], al[3], bh0, bh1);
        }
    }

    // ---- epilogue ----
    if (mat == 2) {
#pragma unroll
        for (int nt = 0; nt < NTB; nt++) {
            int lc = nt * 8 + tig * 2;
            int col = col0 + lc;
            float b0 = biasS[lc], b1 = biasS[lc + 1];
            if (okA)
                *(float2*)&outF[(size_t)rA * D + col] = make_float2(acc[nt][0] + b0, acc[nt][1] + b1);
            if (okB)
                *(float2*)&outF[(size_t)rB * D + col] = make_float2(acc[nt][2] + b0, acc[nt][3] + b1);
        }
    } else {
        float sA = 1.f, sB = 1.f;
        if (mat == 1) {
            sA = okA ? g_dinv[rA] : 0.f;
            sB = okB ? g_dinv[rB] : 0.f;
        }
#pragma unroll
        for (int nt = 0; nt < NTB; nt++) {
            int lc = nt * 8 + tig * 2;
            int col = col0 + lc;
            if (okA)
                *(__half2*)&outH[(size_t)rA * D + col] =
                    __floats2half2_rn(acc[nt][0] * sA, acc[nt][1] * sA);
            if (okB)
                *(__half2*)&outH[(size_t)rB * D + col] =
                    __floats2half2_rn(acc[nt][2] * sB, acc[nt][3] * sB);
        }
    }

    if (mat == 0) {
        float esA = 0.f, edA = 0.f, esB = 0.f, edB = 0.f;
#pragma unroll
        for (int nt = 0; nt < NTB; nt++) {
            int lc = nt * 8 + tig * 2;
            float p0 = a0S[lc], p1 = a0S[lc + 1];
            float q0 = a1S[lc], q1 = a1S[lc + 1];
            esA += acc[nt][0] * p0 + acc[nt][1] * p1;
            edA += acc[nt][0] * q0 + acc[nt][1] * q1;
            esB += acc[nt][2] * p0 + acc[nt][3] * p1;
            edB += acc[nt][2] * q0 + acc[nt][3] * q1;
        }
#pragma unroll
        for (int o = 1; o < 4; o <<= 1) {
            esA += __shfl_xor_sync(0xFFFFFFFFu, esA, o);
            edA += __shfl_xor_sync(0xFFFFFFFFu, edA, o);
            esB += __shfl_xor_sync(0xFFFFFFFFu, esB, o);
            edB += __shfl_xor_sync(0xFFFFFFFFu, edB, o);
        }
        if (tig == 0) {
            int ofs = half * N_NODES;
            if (okA) { g_esp[ofs + rA] = esA; g_edp[ofs + rA] = edA; }
            if (okB) { g_esp[ofs + rB] = esB; g_edp[ofs + rB] = edB; }
        }
    }
}

// ---------------- fused CSR edge gather: softmax denom + message accumulate ----------------
// One warp per destination node. hg/hc are fp16 (half gather traffic); accumulation fp32.
__global__ void __launch_bounds__(256, 8)
edge_gather(int outsel) {
    int d = (blockIdx.x * blockDim.x + threadIdx.x) >> 5;
    int lane = threadIdx.x & 31;
    if (d >= N_NODES) return;
    float* hnew = outsel ? g_bufB : g_bufA;

    int beg = g_rowptr[d];
    int end = g_rowptr[d + 1];
    float edd = g_edp[d] + g_edp[N_NODES + d];
    float dinvd = g_dinv[d];

    // pass 1: softmax denominator
    float sum = 0.f;
    for (int j = beg + lane; j < end; j += 32) {
        int s = g_esrc[j];
        float e = g_esp[s] + g_esp[N_NODES + s] + edd;
        e = (e >= 0.f) ? e : 0.2f * e;
        sum += __expf(e);
    }
#pragma unroll
    for (int o = 16; o > 0; o >>= 1) sum += __shfl_xor_sync(0xFFFFFFFFu, sum, o);
    float inv_denom = 1.0f / sum;

    // pass 2: accumulate messages (warp-cooperative per edge, lanes split D)
    float4 ag = make_float4(0.f, 0.f, 0.f, 0.f);
    float4 ac = make_float4(0.f, 0.f, 0.f, 0.f);
    for (int j = beg; j < end; j++) {
        int s = g_esrc[j];
        float e = g_esp[s] + g_esp[N_NODES + s] + edd;
        e = (e >= 0.f) ? e : 0.2f * e;
        float alpha = __expf(e) * inv_denom;
        float4 vg = ldh4(&g_hg[(size_t)s * D + lane * 4]);
        float4 vc = ldh4(&g_hc[(size_t)s * D + lane * 4]);
        ag.x += alpha * vg.x; ag.y += alpha * vg.y;
        ag.z += alpha * vg.z; ag.w += alpha * vg.w;
        ac.x += vc.x; ac.y += vc.y; ac.z += vc.z; ac.w += vc.w;
    }
    float4 base = *(const float4*)&hnew[(size_t)d * D + lane * 4];
    base.x += ag.x + dinvd * ac.x;
    base.y += ag.y + dinvd * ac.y;
    base.z += ag.z + dinvd * ac.z;
    base.w += ag.w + dinvd * ac.w;
    *(float4*)&hnew[(size_t)d * D + lane * 4] = base;
}

// ---------------- pooling ----------------
__global__ void pool_kernel(const int* __restrict__ batch) {
    int w = (blockIdx.x * blockDim.x + threadIdx.x) >> 5;
    int lane = threadIdx.x & 31;
    int n0 = w * 8;
    if (n0 >= N_NODES) return;
    float4 acc = make_float4(0.f, 0.f, 0.f, 0.f);
    int curg = batch[n0];
    for (int j = 0; j < 8; j++) {
        int n = n0 + j;
        if (n >= N_NODES) break;
        int g = batch[n];
        if (g != curg) {
            atomicAdd((float4*)&g_pooled[(size_t)curg * D + lane * 4], acc);
            acc = make_float4(0.f, 0.f, 0.f, 0.f);
            curg = g;
        }
        float4 v = *(const float4*)&g_bufA[(size_t)n * D + lane * 4];
        acc.x += v.x; acc.y += v.y; acc.z += v.z; acc.w += v.w;
    }
    atomicAdd((float4*)&g_pooled[(size_t)curg * D + lane * 4], acc);
}

__global__ void final_kernel(const float* __restrict__ lin4W, const float* __restrict__ lin4b,
                             float* __restrict__ out) {
    int t = threadIdx.x;
    if (t < NG * 2) {
        int g = t >> 1, o = t & 1;
        float inv = 1.0f / fmaxf(g_cnt[g], 1.0f);
        float sum = 0.f;
        for (int k = 0; k < D; k++) sum += g_pooled[g * D + k] * lin4W[k * 2 + o];
        out[t] = sum * inv + lin4b[o];
    }
}

// ---------------- launch ----------------
extern "C" void kernel_launch(void* const* d_in, const int* in_sizes, int n_in,
                              void* d_out, int out_size) {
    const float* x     = (const float*)d_in[0];
    const float* gatW  = (const float*)d_in[1];
    const float* gata  = (const float*)d_in[2];
    const float* gatb  = (const float*)d_in[3];
    const float* gcnW  = (const float*)d_in[4];
    const float* gcnb  = (const float*)d_in[5];
    const float* linW  = (const float*)d_in[6];
    const float* linb  = (const float*)d_in[7];
    const float* lin4W = (const float*)d_in[8];
    const float* lin4b = (const float*)d_in[9];
    const int*   src   = (const int*)d_in[10];
    const int*   dst   = (const int*)d_in[11];
    const int*   batch = (const int*)d_in[12];
    float* out = (float*)d_out;
    (void)in_sizes; (void)n_in; (void)out_size;

    cudaFuncSetAttribute(gemm8, cudaFuncAttributeMaxDynamicSharedMemorySize, SMEM_TOTAL_G);

    // one-time CSR build + degree norms
    zero_kernel<<<(N_NODES + 255) / 256, 256>>>();
    deg_kernel<<<(ETOT + 255) / 256, 256>>>(dst);
    deg_fin_kernel<<<(N_NODES + 255) / 256, 256>>>(batch);
    scanA<<<SCAN_BLOCKS, 1024>>>();
    scanB<<<1, 32>>>();
    scanC<<<SCAN_BLOCKS, 1024>>>();
    scatter_kernel<<<(ETOT + 255) / 256, 256>>>(src, dst);

    for (int i = 0; i < 3; i++) {
        int insel  = (i == 0) ? 0 : ((i == 1) ? 1 : 2);   // x, bufA, bufB
        int outsel = (i == 1) ? 1 : 0;                    // bufA, bufB, bufA
        int relu   = (i > 0) ? 1 : 0;

        dim3 grid((N_NODES + 127) / 128, 2, 3);
        gemm8<<<grid, 256, SMEM_TOTAL_G>>>(x, insel, relu,
                                           gatW + i * D * D, gcnW + i * D * D, linW + i * D * D,
                                           gatb + i * D, gcnb + i * D, linb + i * D,
                                           gata + i * 2 * D, gata + i * 2 * D + D, outsel);

        edge_gather<<<(N_NODES * 32 + 255) / 256, 256>>>(outsel);
    }

    pool_kernel<<<((N_NODES / 8) * 32 + 255) / 256, 256>>>(batch);
    final_kernel<<<1, 128>>>(lin4W, lin4b, out);
}